// round 11
// baseline (speedup 1.0000x reference)
#include <cuda_runtime.h>
#include <math.h>
#include <stdint.h>

#define TSEQ 2048
#define CEMB 2048
#define BATCH 2
#define NHEAD 16
#define NGRP 4
#define HD 128
#define QKVN 3072          // (16 + 2*4) * 128
#define FFN 8192
#define MROWS 4096         // B*T
#define SCALE 0.08838834764831845f  // 1/sqrt(128)

// ---------------- scratch (device globals: allocation-free rule) -------------
__device__ float g_xn1[MROWS * CEMB];
__device__ float g_xn2[MROWS * CEMB];
__device__ float g_qkv[MROWS * QKVN];
__device__ float g_y  [MROWS * CEMB];
__device__ float g_act[(size_t)MROWS * FFN];
__device__ float g_scores[(size_t)BATCH * NHEAD * TSEQ * TSEQ];
__device__ float g_wcvt[44040192];   // tf32-rounded weights: qkv|proj|fc1|fc2

// ---------------- tf32 / mma / cp.async helpers ------------------------------
__device__ __forceinline__ float to_tf32(float x) {
    asm("cvt.rna.tf32.f32 %0, %0;" : "+f"(x));
    return x;
}

__device__ __forceinline__ void mma8(float c[4], const uint32_t a[4], const uint32_t b[2]) {
    asm volatile(
        "mma.sync.aligned.m16n8k8.row.col.f32.tf32.tf32.f32 "
        "{%0,%1,%2,%3}, {%4,%5,%6,%7}, {%8,%9}, {%0,%1,%2,%3};\n"
        : "+f"(c[0]), "+f"(c[1]), "+f"(c[2]), "+f"(c[3])
        : "r"(a[0]), "r"(a[1]), "r"(a[2]), "r"(a[3]), "r"(b[0]), "r"(b[1]));
}

__device__ __forceinline__ void cp16(uint32_t dst, const void* src) {
    asm volatile("cp.async.cg.shared.global [%0], [%1], 16;" :: "r"(dst), "l"(src));
}
__device__ __forceinline__ void cp_commit() { asm volatile("cp.async.commit_group;"); }
__device__ __forceinline__ void cp_wait2()  { asm volatile("cp.async.wait_group 2;"); }

// ---------------- weight tf32 pre-round --------------------------------------
__global__ void __launch_bounds__(256) cvtw_kernel(
    const float* __restrict__ in, float* __restrict__ outp, int n4)
{
    int i = blockIdx.x * 256 + threadIdx.x;
    if (i >= n4) return;
    float4 v = ((const float4*)in)[i];
    v.x = to_tf32(v.x); v.y = to_tf32(v.y); v.z = to_tf32(v.z); v.w = to_tf32(v.w);
    ((float4*)outp)[i] = v;
}

// ---------------- fused double LayerNorm (tf32-rounded outputs) --------------
__global__ void __launch_bounds__(256) ln_kernel(
    const float* __restrict__ x,
    const float* __restrict__ w1, const float* __restrict__ b1,
    const float* __restrict__ w2, const float* __restrict__ b2)
{
    int row = blockIdx.x, tid = threadIdx.x;
    const float4* xr = (const float4*)(x + (size_t)row * CEMB);
    float4 a = xr[tid], b = xr[tid + 256];

    float s = a.x + a.y + a.z + a.w + b.x + b.y + b.z + b.w;
    float q = a.x*a.x + a.y*a.y + a.z*a.z + a.w*a.w
            + b.x*b.x + b.y*b.y + b.z*b.z + b.w*b.w;
    #pragma unroll
    for (int o = 16; o; o >>= 1) {
        s += __shfl_xor_sync(0xffffffffu, s, o);
        q += __shfl_xor_sync(0xffffffffu, q, o);
    }
    __shared__ float rs[8], rq[8], s_mu, s_rstd;
    int wid = tid >> 5, lane = tid & 31;
    if (!lane) { rs[wid] = s; rq[wid] = q; }
    __syncthreads();
    if (tid == 0) {
        float S = 0.f, Q = 0.f;
        #pragma unroll
        for (int i = 0; i < 8; i++) { S += rs[i]; Q += rq[i]; }
        float mu  = S * (1.0f / CEMB);
        float var = Q * (1.0f / CEMB) - mu * mu;
        s_mu = mu;
        s_rstd = rsqrtf(var + 1e-5f);
    }
    __syncthreads();
    float mu = s_mu, r = s_rstd;

    const float4* W1 = (const float4*)w1; const float4* B1 = (const float4*)b1;
    const float4* W2 = (const float4*)w2; const float4* B2 = (const float4*)b2;
    float4* o1 = (float4*)(g_xn1 + (size_t)row * CEMB);
    float4* o2 = (float4*)(g_xn2 + (size_t)row * CEMB);

    float4 w1a = W1[tid], w1b = W1[tid+256], b1a = B1[tid], b1b = B1[tid+256];
    float4 w2a = W2[tid], w2b = W2[tid+256], b2a = B2[tid], b2b = B2[tid+256];

    float4 na, nb;
    na.x = (a.x-mu)*r; na.y = (a.y-mu)*r; na.z = (a.z-mu)*r; na.w = (a.w-mu)*r;
    nb.x = (b.x-mu)*r; nb.y = (b.y-mu)*r; nb.z = (b.z-mu)*r; nb.w = (b.w-mu)*r;

    float4 t;
    t.x = to_tf32(na.x*w1a.x+b1a.x); t.y = to_tf32(na.y*w1a.y+b1a.y);
    t.z = to_tf32(na.z*w1a.z+b1a.z); t.w = to_tf32(na.w*w1a.w+b1a.w);
    o1[tid] = t;
    t.x = to_tf32(nb.x*w1b.x+b1b.x); t.y = to_tf32(nb.y*w1b.y+b1b.y);
    t.z = to_tf32(nb.z*w1b.z+b1b.z); t.w = to_tf32(nb.w*w1b.w+b1b.w);
    o1[tid+256] = t;
    t.x = to_tf32(na.x*w2a.x+b2a.x); t.y = to_tf32(na.y*w2a.y+b2a.y);
    t.z = to_tf32(na.z*w2a.z+b2a.z); t.w = to_tf32(na.w*w2a.w+b2a.w);
    o2[tid] = t;
    t.x = to_tf32(nb.x*w2b.x+b2b.x); t.y = to_tf32(nb.y*w2b.y+b2b.y);
    t.z = to_tf32(nb.z*w2b.z+b2b.z); t.w = to_tf32(nb.w*w2b.w+b2b.w);
    o2[tid+256] = t;
}

// ---------------- RoPE (in-place, tf32-rounded outputs) ----------------------
__global__ void __launch_bounds__(320) rope_kernel(
    const float* __restrict__ cosb, const float* __restrict__ sinb)
{
    int row = blockIdx.x;
    int t   = row & (TSEQ - 1);
    int tid = threadIdx.x;
    int head = tid >> 4;
    int i    = tid & 15;

    float* base;
    if (head < 16) {
        int g = head >> 2, slot = head & 3;
        base = g_qkv + (size_t)row * QKVN + g * 768 + slot * 128;
    } else {
        int g = head - 16;
        base = g_qkv + (size_t)row * QKVN + g * 768 + 512;
    }
    float c1 = cosb[t*32 + i],      s1 = sinb[t*32 + i];
    float c2 = cosb[t*32 + i + 16], s2 = sinb[t*32 + i + 16];
    float x1 = base[i], x2 = base[i + 16];
    base[i]      = to_tf32(x1 * c1 - x2 * s1);
    base[i + 16] = to_tf32(x2 * c2 + x1 * s2);
}

// ======================= pipelined tf32 GEMM (cp.async, S=4) =================
// Tile 128x128, BK=16, 8 warps (2M x 4N), warp 64x32.
// Stage layout: A[128][20] (flat) then B[16][136] (flat). 4 stages, issue 2 ahead,
// one __syncthreads per iter (overwrite target is 4 iters old; barrier i-3 covers).

enum { EPI_CVT = 0, EPI_RESID = 1, EPI_GELU = 2, EPI_ADDOUT = 3 };

#define AST 2560           // 128*20 floats
#define BST 2176           // 16*136 floats
#define STG (AST + BST)    // 4736 floats = 18944 B
#define MM_SMEM (4 * STG * 4)   // 75776 B

template<int EPI>
__global__ void __launch_bounds__(256, 2) mm_pipe(
    const float* __restrict__ A, int lda,
    const float* __restrict__ B, int ldb,
    float* __restrict__ C, int ldc,
    const float* __restrict__ bias,
    const float* __restrict__ resid,
    int K)
{
    extern __shared__ float sm[];
    const int tid = threadIdx.x, lane = tid & 31, wid = tid >> 5;
    const int wm = (wid >> 2) * 64, wn = (wid & 3) * 32;
    const int lr = lane >> 2, lc = lane & 3;
    const int m0 = blockIdx.y * 128, n0 = blockIdx.x * 128;

    const uint32_t smb = (uint32_t)__cvta_generic_to_shared(sm);

    const int ar0 = tid >> 2,          ak0 = (tid & 3) * 4;
    const int ar1 = (tid + 256) >> 2,  ak1 = ak0;
    const int br0 = tid >> 5,          bn0q = (tid & 31) * 4;
    const int br1 = br0 + 8,           bn1q = bn0q;

    const float* Ab0 = A + (size_t)(m0 + ar0) * lda + ak0;
    const float* Ab1 = A + (size_t)(m0 + ar1) * lda + ak1;
    const float* Bb0 = B + (size_t)br0 * ldb + n0 + bn0q;
    const float* Bb1 = B + (size_t)br1 * ldb + n0 + bn1q;
    const uint32_t Ad0 = smb + (uint32_t)(ar0*20 + ak0) * 4;
    const uint32_t Ad1 = smb + (uint32_t)(ar1*20 + ak1) * 4;
    const uint32_t Bd0 = smb + (uint32_t)(AST + br0*136 + bn0q) * 4;
    const uint32_t Bd1 = smb + (uint32_t)(AST + br1*136 + bn1q) * 4;

    const int nt = K >> 4;

    auto issue = [&](int i) {
        uint32_t so = (uint32_t)(i & 3) * (STG * 4);
        int k0 = i << 4;
        cp16(Ad0 + so, Ab0 + k0);
        cp16(Ad1 + so, Ab1 + k0);
        cp16(Bd0 + so, Bb0 + (size_t)k0 * ldb);
        cp16(Bd1 + so, Bb1 + (size_t)k0 * ldb);
    };

    issue(0); cp_commit();
    issue(1); cp_commit();

    float acc[4][4][4];
    #pragma unroll
    for (int mt = 0; mt < 4; mt++)
        #pragma unroll
        for (int ntt = 0; ntt < 4; ntt++)
            #pragma unroll
            for (int i = 0; i < 4; i++) acc[mt][ntt][i] = 0.f;

    for (int i = 0; i < nt; i++) {
        if (i + 2 < nt) issue(i + 2);
        cp_commit();
        cp_wait2();
        __syncthreads();
        const float* As = sm + (size_t)(i & 3) * STG;
        const float* Bs = As + AST;
        #pragma unroll
        for (int kk = 0; kk < 16; kk += 8) {
            uint32_t afr[4][4], bfr[4][2];
            #pragma unroll
            for (int mt = 0; mt < 4; mt++) {
                int r = wm + mt*16 + lr;
                afr[mt][0] = __float_as_uint(As[r*20     + kk+lc  ]);
                afr[mt][1] = __float_as_uint(As[(r+8)*20 + kk+lc  ]);
                afr[mt][2] = __float_as_uint(As[r*20     + kk+lc+4]);
                afr[mt][3] = __float_as_uint(As[(r+8)*20 + kk+lc+4]);
            }
            #pragma unroll
            for (int ntt = 0; ntt < 4; ntt++) {
                int n = wn + ntt*8 + lr;
                bfr[ntt][0] = __float_as_uint(Bs[(kk+lc  )*136 + n]);
                bfr[ntt][1] = __float_as_uint(Bs[(kk+lc+4)*136 + n]);
            }
            #pragma unroll
            for (int mt = 0; mt < 4; mt++)
                #pragma unroll
                for (int ntt = 0; ntt < 4; ntt++)
                    mma8(acc[mt][ntt], afr[mt], bfr[ntt]);
        }
    }

    #pragma unroll
    for (int mt = 0; mt < 4; mt++) {
        int r = m0 + wm + mt*16 + lr;
        #pragma unroll
        for (int ntt = 0; ntt < 4; ntt++) {
            int cn = n0 + wn + ntt*8 + lc*2;
            float bx = bias[cn], by = bias[cn+1];
            float* p0 = C + (size_t)r * ldc + cn;
            float* p1 = C + (size_t)(r+8) * ldc + cn;
            float v0 = acc[mt][ntt][0] + bx, v1 = acc[mt][ntt][1] + by;
            float v2 = acc[mt][ntt][2] + bx, v3 = acc[mt][ntt][3] + by;
            if (EPI == EPI_RESID) {
                const float* q0 = resid + (size_t)r * ldc + cn;
                const float* q1 = resid + (size_t)(r+8) * ldc + cn;
                v0 += q0[0]; v1 += q0[1]; v2 += q1[0]; v3 += q1[1];
            }
            if (EPI == EPI_GELU) {
                v0 = to_tf32(0.5f*v0*(1.0f + erff(v0*0.70710678118654752f)));
                v1 = to_tf32(0.5f*v1*(1.0f + erff(v1*0.70710678118654752f)));
                v2 = to_tf32(0.5f*v2*(1.0f + erff(v2*0.70710678118654752f)));
                v3 = to_tf32(0.5f*v3*(1.0f + erff(v3*0.70710678118654752f)));
            }
            if (EPI == EPI_ADDOUT) { v0 += p0[0]; v1 += p0[1]; v2 += p1[0]; v3 += p1[1]; }
            if (EPI == EPI_CVT) { v0 = to_tf32(v0); v1 = to_tf32(v1); v2 = to_tf32(v2); v3 = to_tf32(v3); }
            p0[0] = v0; p0[1] = v1; p1[0] = v2; p1[1] = v3;
        }
    }
}

// ---------------- attention: S = Q K^T (pipelined, n-major B) ----------------
#define SC_STG (2 * AST)            // A[128][20] + Bsn[128][20]
#define SC_SMEM (4 * SC_STG * 4)    // 81920 B

__global__ void __launch_bounds__(256, 2) attn_scores_mma()
{
    int si = blockIdx.x, ti = blockIdx.y;
    if (si > ti) return;
    int bh = blockIdx.z;
    int b = bh >> 4, h = bh & 15, g = h >> 2, sl = h & 3;

    const float* Q  = g_qkv + (size_t)b*TSEQ*QKVN + g*768 + sl*128 + (size_t)ti*128*QKVN;
    const float* Kp = g_qkv + (size_t)b*TSEQ*QKVN + g*768 + 512    + (size_t)si*128*QKVN;

    extern __shared__ float sm[];
    const int tid = threadIdx.x, lane = tid & 31, wid = tid >> 5;
    const int wm = (wid >> 2) * 64, wn = (wid & 3) * 32;
    const int lr = lane >> 2, lc = lane & 3;
    const uint32_t smb = (uint32_t)__cvta_generic_to_shared(sm);

    const int r0 = tid >> 2, kq = (tid & 3) * 4, r1 = r0 + 64;
    const float* Aq0 = Q  + (size_t)r0 * QKVN + kq;
    const float* Aq1 = Q  + (size_t)r1 * QKVN + kq;
    const float* Bk0 = Kp + (size_t)r0 * QKVN + kq;
    const float* Bk1 = Kp + (size_t)r1 * QKVN + kq;
    const uint32_t Ad0 = smb + (uint32_t)(r0*20 + kq) * 4;
    const uint32_t Ad1 = smb + (uint32_t)(r1*20 + kq) * 4;
    const uint32_t Bd0 = smb + (uint32_t)(AST + r0*20 + kq) * 4;
    const uint32_t Bd1 = smb + (uint32_t)(AST + r1*20 + kq) * 4;

    auto issue = [&](int i) {
        uint32_t so = (uint32_t)(i & 3) * (SC_STG * 4);
        int k0 = i << 4;
        cp16(Ad0 + so, Aq0 + k0);
        cp16(Ad1 + so, Aq1 + k0);
        cp16(Bd0 + so, Bk0 + k0);
        cp16(Bd1 + so, Bk1 + k0);
    };
    issue(0); cp_commit();
    issue(1); cp_commit();

    float acc[4][4][4];
    #pragma unroll
    for (int mt = 0; mt < 4; mt++)
        #pragma unroll
        for (int ntt = 0; ntt < 4; ntt++)
            #pragma unroll
            for (int i = 0; i < 4; i++) acc[mt][ntt][i] = 0.f;

    for (int i = 0; i < 8; i++) {        // HD/16
        if (i + 2 < 8) issue(i + 2);
        cp_commit();
        cp_wait2();
        __syncthreads();
        const float* As  = sm + (size_t)(i & 3) * SC_STG;
        const float* Bsn = As + AST;
        #pragma unroll
        for (int kk = 0; kk < 16; kk += 8) {
            uint32_t afr[4][4], bfr[4][2];
            #pragma unroll
            for (int mt = 0; mt < 4; mt++) {
                int r = wm + mt*16 + lr;
                afr[mt][0] = __float_as_uint(As[r*20     + kk+lc  ]);
                afr[mt][1] = __float_as_uint(As[(r+8)*20 + kk+lc  ]);
                afr[mt][2] = __float_as_uint(As[r*20     + kk+lc+4]);
                afr[mt][3] = __float_as_uint(As[(r+8)*20 + kk+lc+4]);
            }
            #pragma unroll
            for (int ntt = 0; ntt < 4; ntt++) {
                int n = wn + ntt*8 + lr;
                bfr[ntt][0] = __float_as_uint(Bsn[n*20 + kk+lc  ]);
                bfr[ntt][1] = __float_as_uint(Bsn[n*20 + kk+lc+4]);
            }
            #pragma unroll
            for (int mt = 0; mt < 4; mt++)
                #pragma unroll
                for (int ntt = 0; ntt < 4; ntt++)
                    mma8(acc[mt][ntt], afr[mt], bfr[ntt]);
        }
    }

    float* S = g_scores + (size_t)bh * TSEQ * TSEQ;
    #pragma unroll
    for (int mt = 0; mt < 4; mt++) {
        int t0 = ti*128 + wm + mt*16 + lr;
        int t1 = t0 + 8;
        #pragma unroll
        for (int ntt = 0; ntt < 4; ntt++) {
            int s0 = si*128 + wn + ntt*8 + lc*2;
            S[(size_t)t0*TSEQ + s0  ] = (s0   <= t0) ? acc[mt][ntt][0]*SCALE : -3.0e38f;
            S[(size_t)t0*TSEQ + s0+1] = (s0+1 <= t0) ? acc[mt][ntt][1]*SCALE : -3.0e38f;
            S[(size_t)t1*TSEQ + s0  ] = (s0   <= t1) ? acc[mt][ntt][2]*SCALE : -3.0e38f;
            S[(size_t)t1*TSEQ + s0+1] = (s0+1 <= t1) ? acc[mt][ntt][3]*SCALE : -3.0e38f;
        }
    }
}

// ---------------- row softmax (tf32-rounded P) -------------------------------
__global__ void __launch_bounds__(128) softmax_kernel()
{
    int t = blockIdx.x, bh = blockIdx.y;
    float* row = g_scores + ((size_t)bh * TSEQ + t) * TSEQ;
    int cnt = (t >> 7) + 1;
    int tid = threadIdx.x;

    float v[16];
    float mx = -3.4e38f;
    #pragma unroll
    for (int c = 0; c < 16; c++)
        if (c < cnt) { v[c] = row[c*128 + tid]; mx = fmaxf(mx, v[c]); }
    #pragma unroll
    for (int o = 16; o; o >>= 1) mx = fmaxf(mx, __shfl_xor_sync(0xffffffffu, mx, o));

    __shared__ float sm1[4], sm2[4];
    int wid = tid >> 5, lane = tid & 31;
    if (!lane) sm1[wid] = mx;
    __syncthreads();
    mx = fmaxf(fmaxf(sm1[0], sm1[1]), fmaxf(sm1[2], sm1[3]));

    float s = 0.f;
    #pragma unroll
    for (int c = 0; c < 16; c++)
        if (c < cnt) { v[c] = __expf(v[c] - mx); s += v[c]; }
    #pragma unroll
    for (int o = 16; o; o >>= 1) s += __shfl_xor_sync(0xffffffffu, s, o);
    if (!lane) sm2[wid] = s;
    __syncthreads();
    s = sm2[0] + sm2[1] + sm2[2] + sm2[3];

    float inv = 1.0f / s;
    #pragma unroll
    for (int c = 0; c < 16; c++)
        if (c < cnt) row[c*128 + tid] = to_tf32(v[c] * inv);
}

// ---------------- attention: Y = P V (pipelined, triangular) -----------------
__global__ void __launch_bounds__(256, 2) attn_av_mma()
{
    int ti = blockIdx.x, bh = blockIdx.y;
    int b = bh >> 4, h = bh & 15, g = h >> 2;

    const float* P = g_scores + (size_t)bh * TSEQ * TSEQ + (size_t)ti*128 * TSEQ;
    const float* V = g_qkv + (size_t)b*TSEQ*QKVN + g*768 + 640;

    extern __shared__ float sm[];
    const int tid = threadIdx.x, lane = tid & 31, wid = tid >> 5;
    const int wm = (wid >> 2) * 64, wn = (wid & 3) * 32;
    const int lr = lane >> 2, lc = lane & 3;
    const uint32_t smb = (uint32_t)__cvta_generic_to_shared(sm);

    const int ar0 = tid >> 2,          ak0 = (tid & 3) * 4;
    const int ar1 = ar0 + 64;
    const int br0 = tid >> 5,          bn0q = (tid & 31) * 4;
    const int br1 = br0 + 8;

    const float* Ab0 = P + (size_t)ar0 * TSEQ + ak0;
    const float* Ab1 = P + (size_t)ar1 * TSEQ + ak0;
    const float* Bb0 = V + (size_t)br0 * QKVN + bn0q;
    const float* Bb1 = V + (size_t)br1 * QKVN + bn0q;
    const uint32_t Ad0 = smb + (uint32_t)(ar0*20 + ak0) * 4;
    const uint32_t Ad1 = smb + (uint32_t)(ar1*20 + ak0) * 4;
    const uint32_t Bd0 = smb + (uint32_t)(AST + br0*136 + bn0q) * 4;
    const uint32_t Bd1 = smb + (uint32_t)(AST + br1*136 + bn0q) * 4;

    const int nt = (ti + 1) * 8;

    auto issue = [&](int i) {
        uint32_t so = (uint32_t)(i & 3) * (STG * 4);
        int k0 = i << 4;
        cp16(Ad0 + so, Ab0 + k0);
        cp16(Ad1 + so, Ab1 + k0);
        cp16(Bd0 + so, Bb0 + (size_t)k0 * QKVN);
        cp16(Bd1 + so, Bb1 + (size_t)k0 * QKVN);
    };
    issue(0); cp_commit();
    issue(1); cp_commit();

    float acc[4][4][4];
    #pragma unroll
    for (int mt = 0; mt < 4; mt++)
        #pragma unroll
        for (int ntt = 0; ntt < 4; ntt++)
            #pragma unroll
            for (int i = 0; i < 4; i++) acc[mt][ntt][i] = 0.f;

    for (int i = 0; i < nt; i++) {
        if (i + 2 < nt) issue(i + 2);
        cp_commit();
        cp_wait2();
        __syncthreads();
        const float* As = sm + (size_t)(i & 3) * STG;
        const float* Bs = As + AST;
        #pragma unroll
        for (int kk = 0; kk < 16; kk += 8) {
            uint32_t afr[4][4], bfr[4][2];
            #pragma unroll
            for (int mt = 0; mt < 4; mt++) {
                int r = wm + mt*16 + lr;
                afr[mt][0] = __float_as_uint(As[r*20     + kk+lc  ]);
                afr[mt][1] = __float_as_uint(As[(r+8)*20 + kk+lc  ]);
                afr[mt][2] = __float_as_uint(As[r*20     + kk+lc+4]);
                afr[mt][3] = __float_as_uint(As[(r+8)*20 + kk+lc+4]);
            }
            #pragma unroll
            for (int ntt = 0; ntt < 4; ntt++) {
                int n = wn + ntt*8 + lr;
                bfr[ntt][0] = __float_as_uint(Bs[(kk+lc  )*136 + n]);
                bfr[ntt][1] = __float_as_uint(Bs[(kk+lc+4)*136 + n]);
            }
            #pragma unroll
            for (int mt = 0; mt < 4; mt++)
                #pragma unroll
                for (int ntt = 0; ntt < 4; ntt++)
                    mma8(acc[mt][ntt], afr[mt], bfr[ntt]);
        }
    }

    float* Y = g_y + (size_t)(b*TSEQ + ti*128) * CEMB + h*128;
    #pragma unroll
    for (int mt = 0; mt < 4; mt++) {
        int r0 = wm + mt*16 + lr;
        #pragma unroll
        for (int ntt = 0; ntt < 4; ntt++) {
            int dd = wn + ntt*8 + lc*2;
            Y[(size_t)r0*CEMB + dd  ]     = to_tf32(acc[mt][ntt][0]);
            Y[(size_t)r0*CEMB + dd+1]     = to_tf32(acc[mt][ntt][1]);
            Y[(size_t)(r0+8)*CEMB + dd  ] = to_tf32(acc[mt][ntt][2]);
            Y[(size_t)(r0+8)*CEMB + dd+1] = to_tf32(acc[mt][ntt][3]);
        }
    }
}

// ---------------- launch ----------------------------------------------------
extern "C" void kernel_launch(void* const* d_in, const int* in_sizes, int n_in,
                              void* d_out, int out_size)
{
    (void)in_sizes; (void)n_in; (void)out_size;
    const float* x     = (const float*)d_in[0];
    const float* cosb  = (const float*)d_in[1];
    const float* sinb  = (const float*)d_in[2];
    const float* ln1w  = (const float*)d_in[3];
    const float* ln1b  = (const float*)d_in[4];
    const float* wqkv  = (const float*)d_in[5];
    const float* bqkv  = (const float*)d_in[6];
    const float* wproj = (const float*)d_in[7];
    const float* bproj = (const float*)d_in[8];
    const float* ln2w  = (const float*)d_in[9];
    const float* ln2b  = (const float*)d_in[10];
    const float* wfc1  = (const float*)d_in[11];
    const float* bfc1  = (const float*)d_in[12];
    const float* wfc2  = (const float*)d_in[13];
    const float* bfc2  = (const float*)d_in[14];
    float* out = (float*)d_out;

    float *xn1, *xn2, *qkv, *yv, *act, *wc;
    cudaGetSymbolAddress((void**)&xn1, g_xn1);
    cudaGetSymbolAddress((void**)&xn2, g_xn2);
    cudaGetSymbolAddress((void**)&qkv, g_qkv);
    cudaGetSymbolAddress((void**)&yv,  g_y);
    cudaGetSymbolAddress((void**)&act, g_act);
    cudaGetSymbolAddress((void**)&wc,  g_wcvt);
    float* wqkv_c  = wc;
    float* wproj_c = wc + 6291456;
    float* wfc1_c  = wc + 10485760;
    float* wfc2_c  = wc + 27262976;

    cudaFuncSetAttribute(mm_pipe<EPI_CVT>,    cudaFuncAttributeMaxDynamicSharedMemorySize, MM_SMEM);
    cudaFuncSetAttribute(mm_pipe<EPI_RESID>,  cudaFuncAttributeMaxDynamicSharedMemorySize, MM_SMEM);
    cudaFuncSetAttribute(mm_pipe<EPI_GELU>,   cudaFuncAttributeMaxDynamicSharedMemorySize, MM_SMEM);
    cudaFuncSetAttribute(mm_pipe<EPI_ADDOUT>, cudaFuncAttributeMaxDynamicSharedMemorySize, MM_SMEM);
    cudaFuncSetAttribute(attn_scores_mma,     cudaFuncAttributeMaxDynamicSharedMemorySize, SC_SMEM);
    cudaFuncSetAttribute(attn_av_mma,         cudaFuncAttributeMaxDynamicSharedMemorySize, MM_SMEM);

    // 0. tf32-round all weights once per call
    cvtw_kernel<<<6144, 256>>>(wqkv,  wqkv_c,  1572864);
    cvtw_kernel<<<4096, 256>>>(wproj, wproj_c, 1048576);
    cvtw_kernel<<<16384, 256>>>(wfc1, wfc1_c,  4194304);
    cvtw_kernel<<<16384, 256>>>(wfc2, wfc2_c,  4194304);

    // 1. LN1 + LN2 (shared statistics, tf32-rounded outputs)
    ln_kernel<<<MROWS, 256>>>(x, ln1w, ln1b, ln2w, ln2b);

    // 2. QKV GEMM (tf32-rounded output for attention consumers)
    mm_pipe<EPI_CVT><<<dim3(QKVN/128, MROWS/128), 256, MM_SMEM>>>(
        xn1, CEMB, wqkv_c, QKVN, qkv, QKVN, bqkv, nullptr, CEMB);

    // 3. RoPE in-place
    rope_kernel<<<MROWS, 320>>>(cosb, sinb);

    // 4-6. causal scores, softmax, P·V
    attn_scores_mma<<<dim3(16, 16, BATCH*NHEAD), 256, SC_SMEM>>>();
    softmax_kernel<<<dim3(TSEQ, BATCH*NHEAD), 128>>>();
    attn_av_mma<<<dim3(16, BATCH*NHEAD), 256, MM_SMEM>>>();

    // 7. proj GEMM (+b_proj + x residual) -> d_out
    mm_pipe<EPI_RESID><<<dim3(CEMB/128, MROWS/128), 256, MM_SMEM>>>(
        yv, CEMB, wproj_c, CEMB, out, CEMB, bproj, x, CEMB);

    // 8. fc1 GEMM + exact GELU (tf32-rounded)
    mm_pipe<EPI_GELU><<<dim3(FFN/128, MROWS/128), 256, MM_SMEM>>>(
        xn2, CEMB, wfc1_c, FFN, act, FFN, bfc1, nullptr, CEMB);

    // 9. fc2 GEMM adds into d_out
    mm_pipe<EPI_ADDOUT><<<dim3(CEMB/128, MROWS/128), 256, MM_SMEM>>>(
        act, FFN, wfc2_c, CEMB, out, CEMB, bfc2, nullptr, FFN);
}

// round 12
// speedup vs baseline: 1.0147x; 1.0147x over previous
#include <cuda_runtime.h>
#include <math.h>
#include <stdint.h>

#define TSEQ 2048
#define CEMB 2048
#define BATCH 2
#define NHEAD 16
#define NGRP 4
#define HD 128
#define QKVN 3072          // (16 + 2*4) * 128
#define FFN 8192
#define MROWS 4096         // B*T
#define SCALE 0.08838834764831845f  // 1/sqrt(128)

// ---------------- scratch (device globals: allocation-free rule) -------------
__device__ float g_xn1[MROWS * CEMB];
__device__ float g_xn2[MROWS * CEMB];
__device__ float g_qkv[MROWS * QKVN];
__device__ float g_y  [MROWS * CEMB];
__device__ float g_act[(size_t)MROWS * FFN];
__device__ float g_scores[(size_t)BATCH * NHEAD * TSEQ * TSEQ];
__device__ float g_wcvt[44040192];   // tf32-rounded TRANSPOSED weights
__device__ float g_vt[(size_t)BATCH * NGRP * HD * TSEQ];  // V transposed [b*g][d][s]

// ---------------- tf32 / mma / cp.async helpers ------------------------------
__device__ __forceinline__ float to_tf32(float x) {
    asm("cvt.rna.tf32.f32 %0, %0;" : "+f"(x));
    return x;
}

__device__ __forceinline__ void mma8(float c[4], const uint32_t a[4], const uint32_t b[2]) {
    asm volatile(
        "mma.sync.aligned.m16n8k8.row.col.f32.tf32.tf32.f32 "
        "{%0,%1,%2,%3}, {%4,%5,%6,%7}, {%8,%9}, {%0,%1,%2,%3};\n"
        : "+f"(c[0]), "+f"(c[1]), "+f"(c[2]), "+f"(c[3])
        : "r"(a[0]), "r"(a[1]), "r"(a[2]), "r"(a[3]), "r"(b[0]), "r"(b[1]));
}

__device__ __forceinline__ void cp16(uint32_t dst, const void* src) {
    asm volatile("cp.async.cg.shared.global [%0], [%1], 16;" :: "r"(dst), "l"(src));
}
__device__ __forceinline__ void cp_commit() { asm volatile("cp.async.commit_group;"); }
__device__ __forceinline__ void cp_wait2()  { asm volatile("cp.async.wait_group 2;"); }

// ---------------- weight tf32 round + transpose [K][N] -> [N][K] -------------
__global__ void __launch_bounds__(256) wtrans_kernel(
    const float* __restrict__ in, float* __restrict__ outp, int K, int N)
{
    __shared__ float t[32][33];
    int nb = blockIdx.x * 32, kb = blockIdx.y * 32;
    int tx = threadIdx.x & 31, ty = threadIdx.x >> 5;
    #pragma unroll
    for (int i = 0; i < 4; i++)
        t[ty + i*8][tx] = in[(size_t)(kb + ty + i*8) * N + nb + tx];
    __syncthreads();
    #pragma unroll
    for (int i = 0; i < 4; i++)
        outp[(size_t)(nb + ty + i*8) * K + kb + tx] = to_tf32(t[tx][ty + i*8]);
}

// ---------------- V transpose: g_qkv v-slices -> g_vt[bg][d][s] --------------
__global__ void __launch_bounds__(256) vtrans_kernel()
{
    __shared__ float t[32][33];
    int z = blockIdx.z;                 // b*4 + g
    int b = z >> 2, g = z & 3;
    int sb = blockIdx.x * 32, db = blockIdx.y * 32;
    int tx = threadIdx.x & 31, ty = threadIdx.x >> 5;
    #pragma unroll
    for (int i = 0; i < 4; i++)
        t[ty + i*8][tx] = g_qkv[(size_t)(b*TSEQ + sb + ty + i*8) * QKVN + g*768 + 640 + db + tx];
    __syncthreads();
    #pragma unroll
    for (int i = 0; i < 4; i++)
        g_vt[((size_t)z * HD + db + ty + i*8) * TSEQ + sb + tx] = t[tx][ty + i*8];
}

// ---------------- fused double LayerNorm (tf32-rounded outputs) --------------
__global__ void __launch_bounds__(256) ln_kernel(
    const float* __restrict__ x,
    const float* __restrict__ w1, const float* __restrict__ b1,
    const float* __restrict__ w2, const float* __restrict__ b2)
{
    int row = blockIdx.x, tid = threadIdx.x;
    const float4* xr = (const float4*)(x + (size_t)row * CEMB);
    float4 a = xr[tid], b = xr[tid + 256];

    float s = a.x + a.y + a.z + a.w + b.x + b.y + b.z + b.w;
    float q = a.x*a.x + a.y*a.y + a.z*a.z + a.w*a.w
            + b.x*b.x + b.y*b.y + b.z*b.z + b.w*b.w;
    #pragma unroll
    for (int o = 16; o; o >>= 1) {
        s += __shfl_xor_sync(0xffffffffu, s, o);
        q += __shfl_xor_sync(0xffffffffu, q, o);
    }
    __shared__ float rs[8], rq[8], s_mu, s_rstd;
    int wid = tid >> 5, lane = tid & 31;
    if (!lane) { rs[wid] = s; rq[wid] = q; }
    __syncthreads();
    if (tid == 0) {
        float S = 0.f, Q = 0.f;
        #pragma unroll
        for (int i = 0; i < 8; i++) { S += rs[i]; Q += rq[i]; }
        float mu  = S * (1.0f / CEMB);
        float var = Q * (1.0f / CEMB) - mu * mu;
        s_mu = mu;
        s_rstd = rsqrtf(var + 1e-5f);
    }
    __syncthreads();
    float mu = s_mu, r = s_rstd;

    const float4* W1 = (const float4*)w1; const float4* B1 = (const float4*)b1;
    const float4* W2 = (const float4*)w2; const float4* B2 = (const float4*)b2;
    float4* o1 = (float4*)(g_xn1 + (size_t)row * CEMB);
    float4* o2 = (float4*)(g_xn2 + (size_t)row * CEMB);

    float4 w1a = W1[tid], w1b = W1[tid+256], b1a = B1[tid], b1b = B1[tid+256];
    float4 w2a = W2[tid], w2b = W2[tid+256], b2a = B2[tid], b2b = B2[tid+256];

    float4 na, nb;
    na.x = (a.x-mu)*r; na.y = (a.y-mu)*r; na.z = (a.z-mu)*r; na.w = (a.w-mu)*r;
    nb.x = (b.x-mu)*r; nb.y = (b.y-mu)*r; nb.z = (b.z-mu)*r; nb.w = (b.w-mu)*r;

    float4 t;
    t.x = to_tf32(na.x*w1a.x+b1a.x); t.y = to_tf32(na.y*w1a.y+b1a.y);
    t.z = to_tf32(na.z*w1a.z+b1a.z); t.w = to_tf32(na.w*w1a.w+b1a.w);
    o1[tid] = t;
    t.x = to_tf32(nb.x*w1b.x+b1b.x); t.y = to_tf32(nb.y*w1b.y+b1b.y);
    t.z = to_tf32(nb.z*w1b.z+b1b.z); t.w = to_tf32(nb.w*w1b.w+b1b.w);
    o1[tid+256] = t;
    t.x = to_tf32(na.x*w2a.x+b2a.x); t.y = to_tf32(na.y*w2a.y+b2a.y);
    t.z = to_tf32(na.z*w2a.z+b2a.z); t.w = to_tf32(na.w*w2a.w+b2a.w);
    o2[tid] = t;
    t.x = to_tf32(nb.x*w2b.x+b2b.x); t.y = to_tf32(nb.y*w2b.y+b2b.y);
    t.z = to_tf32(nb.z*w2b.z+b2b.z); t.w = to_tf32(nb.w*w2b.w+b2b.w);
    o2[tid+256] = t;
}

// ---------------- RoPE (in-place, tf32-rounded outputs) ----------------------
__global__ void __launch_bounds__(320) rope_kernel(
    const float* __restrict__ cosb, const float* __restrict__ sinb)
{
    int row = blockIdx.x;
    int t   = row & (TSEQ - 1);
    int tid = threadIdx.x;
    int head = tid >> 4;
    int i    = tid & 15;

    float* base;
    if (head < 16) {
        int g = head >> 2, slot = head & 3;
        base = g_qkv + (size_t)row * QKVN + g * 768 + slot * 128;
    } else {
        int g = head - 16;
        base = g_qkv + (size_t)row * QKVN + g * 768 + 512;
    }
    float c1 = cosb[t*32 + i],      s1 = sinb[t*32 + i];
    float c2 = cosb[t*32 + i + 16], s2 = sinb[t*32 + i + 16];
    float x1 = base[i], x2 = base[i + 16];
    base[i]      = to_tf32(x1 * c1 - x2 * s1);
    base[i + 16] = to_tf32(x2 * c2 + x1 * s2);
}

// ======================= vectorized-fragment tf32 GEMM =======================
// Tile 128x128, BK=16, 8 warps (2M x 4N), warp 64x32.
// A smem m-major [128][16], B smem n-major [128][16]; pitch 16 -> LDS.128
// conflict-free (rows R,R+1 split banks 0-15/16-31 per phase).
// k-permutation: thread lc's float4 (data k 4lc..4lc+3) feeds
//   call0: hw lc <- j0, hw lc+4 <- j1 ; call1: j2, j3  (A and B agree).
// cp.async 4-stage, issue 2 ahead, one __syncthreads per iter.

enum { EPI_CVT = 0, EPI_RESID = 1, EPI_GELU = 2, EPI_ADDOUT = 3 };

#define ASTN 2048          // 128*16 floats
#define STG  4096          // A + B floats per stage = 16384 B
#define MM_SMEM (4 * STG * 4)   // 65536 B

// Shared mainloop compute for one stage (operand-major layouts).
__device__ __forceinline__ void stage_mma(
    const float* As, const float* Bs, int wm, int wn, int lr, int lc,
    float acc[4][4][4])
{
    float4 bv[4];
    #pragma unroll
    for (int ntt = 0; ntt < 4; ntt++)
        bv[ntt] = *(const float4*)&Bs[(wn + ntt*8 + lr)*16 + lc*4];
    #pragma unroll
    for (int mt = 0; mt < 4; mt++) {
        float4 alo = *(const float4*)&As[(wm + mt*16 + lr)*16 + lc*4];
        float4 ahi = *(const float4*)&As[(wm + mt*16 + 8 + lr)*16 + lc*4];
        uint32_t a0[4] = { __float_as_uint(alo.x), __float_as_uint(ahi.x),
                           __float_as_uint(alo.y), __float_as_uint(ahi.y) };
        uint32_t a1[4] = { __float_as_uint(alo.z), __float_as_uint(ahi.z),
                           __float_as_uint(alo.w), __float_as_uint(ahi.w) };
        #pragma unroll
        for (int ntt = 0; ntt < 4; ntt++) {
            uint32_t b0[2] = { __float_as_uint(bv[ntt].x), __float_as_uint(bv[ntt].y) };
            mma8(acc[mt][ntt], a0, b0);
        }
        #pragma unroll
        for (int ntt = 0; ntt < 4; ntt++) {
            uint32_t b1[2] = { __float_as_uint(bv[ntt].z), __float_as_uint(bv[ntt].w) };
            mma8(acc[mt][ntt], a1, b1);
        }
    }
}

template<int EPI>
__global__ void __launch_bounds__(256, 2) mm_pipe(
    const float* __restrict__ A,      // [M][K] row-major
    const float* __restrict__ Bt,     // [N][K] row-major (transposed weights)
    float* __restrict__ C, int ldc,
    const float* __restrict__ bias,
    const float* __restrict__ resid,
    int K)
{
    extern __shared__ float sm[];
    const int tid = threadIdx.x, lane = tid & 31, wid = tid >> 5;
    const int wm = (wid >> 2) * 64, wn = (wid & 3) * 32;
    const int lr = lane >> 2, lc = lane & 3;
    const int m0 = blockIdx.y * 128, n0 = blockIdx.x * 128;
    const uint32_t smb = (uint32_t)__cvta_generic_to_shared(sm);

    const int r0 = tid >> 2,        cq0 = (tid & 3) * 4;
    const int r1 = (tid + 256) >> 2;
    const float* Asrc0 = A  + (size_t)(m0 + r0) * K + cq0;
    const float* Asrc1 = A  + (size_t)(m0 + r1) * K + cq0;
    const float* Bsrc0 = Bt + (size_t)(n0 + r0) * K + cq0;
    const float* Bsrc1 = Bt + (size_t)(n0 + r1) * K + cq0;
    const uint32_t Ad0 = smb + (uint32_t)(r0*16 + cq0) * 4;
    const uint32_t Ad1 = smb + (uint32_t)(r1*16 + cq0) * 4;
    const uint32_t Bd0 = smb + (uint32_t)(ASTN + r0*16 + cq0) * 4;
    const uint32_t Bd1 = smb + (uint32_t)(ASTN + r1*16 + cq0) * 4;

    const int nt = K >> 4;
    auto issue = [&](int i) {
        uint32_t so = (uint32_t)(i & 3) * (STG * 4);
        int k0 = i << 4;
        cp16(Ad0 + so, Asrc0 + k0);
        cp16(Ad1 + so, Asrc1 + k0);
        cp16(Bd0 + so, Bsrc0 + k0);
        cp16(Bd1 + so, Bsrc1 + k0);
    };
    issue(0); cp_commit();
    issue(1); cp_commit();

    float acc[4][4][4];
    #pragma unroll
    for (int mt = 0; mt < 4; mt++)
        #pragma unroll
        for (int ntt = 0; ntt < 4; ntt++)
            #pragma unroll
            for (int i = 0; i < 4; i++) acc[mt][ntt][i] = 0.f;

    for (int i = 0; i < nt; i++) {
        if (i + 2 < nt) issue(i + 2);
        cp_commit();
        cp_wait2();
        __syncthreads();
        const float* As = sm + (size_t)(i & 3) * STG;
        stage_mma(As, As + ASTN, wm, wn, lr, lc, acc);
    }

    #pragma unroll
    for (int mt = 0; mt < 4; mt++) {
        int r = m0 + wm + mt*16 + lr;
        #pragma unroll
        for (int ntt = 0; ntt < 4; ntt++) {
            int cn = n0 + wn + ntt*8 + lc*2;
            float bx = bias[cn], by = bias[cn+1];
            float* p0 = C + (size_t)r * ldc + cn;
            float* p1 = C + (size_t)(r+8) * ldc + cn;
            float v0 = acc[mt][ntt][0] + bx, v1 = acc[mt][ntt][1] + by;
            float v2 = acc[mt][ntt][2] + bx, v3 = acc[mt][ntt][3] + by;
            if (EPI == EPI_RESID) {
                const float* q0 = resid + (size_t)r * ldc + cn;
                const float* q1 = resid + (size_t)(r+8) * ldc + cn;
                v0 += q0[0]; v1 += q0[1]; v2 += q1[0]; v3 += q1[1];
            }
            if (EPI == EPI_GELU) {
                v0 = to_tf32(0.5f*v0*(1.0f + erff(v0*0.70710678118654752f)));
                v1 = to_tf32(0.5f*v1*(1.0f + erff(v1*0.70710678118654752f)));
                v2 = to_tf32(0.5f*v2*(1.0f + erff(v2*0.70710678118654752f)));
                v3 = to_tf32(0.5f*v3*(1.0f + erff(v3*0.70710678118654752f)));
            }
            if (EPI == EPI_ADDOUT) { v0 += p0[0]; v1 += p0[1]; v2 += p1[0]; v3 += p1[1]; }
            if (EPI == EPI_CVT) { v0 = to_tf32(v0); v1 = to_tf32(v1); v2 = to_tf32(v2); v3 = to_tf32(v3); }
            p0[0] = v0; p0[1] = v1; p1[0] = v2; p1[1] = v3;
        }
    }
}

// ---------------- attention: S = Q K^T (both operand-major naturally) --------
__global__ void __launch_bounds__(256, 2) attn_scores_mma()
{
    int si = blockIdx.x, ti = blockIdx.y;
    if (si > ti) return;
    int bh = blockIdx.z;
    int b = bh >> 4, h = bh & 15, g = h >> 2, sl = h & 3;

    const float* Q  = g_qkv + (size_t)b*TSEQ*QKVN + g*768 + sl*128 + (size_t)ti*128*QKVN;
    const float* Kp = g_qkv + (size_t)b*TSEQ*QKVN + g*768 + 512    + (size_t)si*128*QKVN;

    extern __shared__ float sm[];
    const int tid = threadIdx.x, lane = tid & 31, wid = tid >> 5;
    const int wm = (wid >> 2) * 64, wn = (wid & 3) * 32;
    const int lr = lane >> 2, lc = lane & 3;
    const uint32_t smb = (uint32_t)__cvta_generic_to_shared(sm);

    const int r0 = tid >> 2,        cq0 = (tid & 3) * 4;
    const int r1 = (tid + 256) >> 2;
    const float* Asrc0 = Q  + (size_t)r0 * QKVN + cq0;
    const float* Asrc1 = Q  + (size_t)r1 * QKVN + cq0;
    const float* Bsrc0 = Kp + (size_t)r0 * QKVN + cq0;
    const float* Bsrc1 = Kp + (size_t)r1 * QKVN + cq0;
    const uint32_t Ad0 = smb + (uint32_t)(r0*16 + cq0) * 4;
    const uint32_t Ad1 = smb + (uint32_t)(r1*16 + cq0) * 4;
    const uint32_t Bd0 = smb + (uint32_t)(ASTN + r0*16 + cq0) * 4;
    const uint32_t Bd1 = smb + (uint32_t)(ASTN + r1*16 + cq0) * 4;

    auto issue = [&](int i) {
        uint32_t so = (uint32_t)(i & 3) * (STG * 4);
        int k0 = i << 4;
        cp16(Ad0 + so, Asrc0 + k0);
        cp16(Ad1 + so, Asrc1 + k0);
        cp16(Bd0 + so, Bsrc0 + k0);
        cp16(Bd1 + so, Bsrc1 + k0);
    };
    issue(0); cp_commit();
    issue(1); cp_commit();

    float acc[4][4][4];
    #pragma unroll
    for (int mt = 0; mt < 4; mt++)
        #pragma unroll
        for (int ntt = 0; ntt < 4; ntt++)
            #pragma unroll
            for (int i = 0; i < 4; i++) acc[mt][ntt][i] = 0.f;

    for (int i = 0; i < 8; i++) {      // HD/16
        if (i + 2 < 8) issue(i + 2);
        cp_commit();
        cp_wait2();
        __syncthreads();
        const float* As = sm + (size_t)(i & 3) * STG;
        stage_mma(As, As + ASTN, wm, wn, lr, lc, acc);
    }

    float* S = g_scores + (size_t)bh * TSEQ * TSEQ;
    #pragma unroll
    for (int mt = 0; mt < 4; mt++) {
        int t0 = ti*128 + wm + mt*16 + lr;
        int t1 = t0 + 8;
        #pragma unroll
        for (int ntt = 0; ntt < 4; ntt++) {
            int s0 = si*128 + wn + ntt*8 + lc*2;
            S[(size_t)t0*TSEQ + s0  ] = (s0   <= t0) ? acc[mt][ntt][0]*SCALE : -3.0e38f;
            S[(size_t)t0*TSEQ + s0+1] = (s0+1 <= t0) ? acc[mt][ntt][1]*SCALE : -3.0e38f;
            S[(size_t)t1*TSEQ + s0  ] = (s0   <= t1) ? acc[mt][ntt][2]*SCALE : -3.0e38f;
            S[(size_t)t1*TSEQ + s0+1] = (s0+1 <= t1) ? acc[mt][ntt][3]*SCALE : -3.0e38f;
        }
    }
}

// ---------------- row softmax (tf32-rounded P) -------------------------------
__global__ void __launch_bounds__(128) softmax_kernel()
{
    int t = blockIdx.x, bh = blockIdx.y;
    float* row = g_scores + ((size_t)bh * TSEQ + t) * TSEQ;
    int cnt = (t >> 7) + 1;
    int tid = threadIdx.x;

    float v[16];
    float mx = -3.4e38f;
    #pragma unroll
    for (int c = 0; c < 16; c++)
        if (c < cnt) { v[c] = row[c*128 + tid]; mx = fmaxf(mx, v[c]); }
    #pragma unroll
    for (int o = 16; o; o >>= 1) mx = fmaxf(mx, __shfl_xor_sync(0xffffffffu, mx, o));

    __shared__ float sm1[4], sm2[4];
    int wid = tid >> 5, lane = tid & 31;
    if (!lane) sm1[wid] = mx;
    __syncthreads();
    mx = fmaxf(fmaxf(sm1[0], sm1[1]), fmaxf(sm1[2], sm1[3]));

    float s = 0.f;
    #pragma unroll
    for (int c = 0; c < 16; c++)
        if (c < cnt) { v[c] = __expf(v[c] - mx); s += v[c]; }
    #pragma unroll
    for (int o = 16; o; o >>= 1) s += __shfl_xor_sync(0xffffffffu, s, o);
    if (!lane) sm2[wid] = s;
    __syncthreads();
    s = sm2[0] + sm2[1] + sm2[2] + sm2[3];

    float inv = 1.0f / s;
    #pragma unroll
    for (int c = 0; c < 16; c++)
        if (c < cnt) row[c*128 + tid] = to_tf32(v[c] * inv);
}

// ---------------- attention: Y = P V (P m-major, Vt n-major) -----------------
__global__ void __launch_bounds__(256, 2) attn_av_mma()
{
    int ti = blockIdx.x, bh = blockIdx.y;
    int b = bh >> 4, h = bh & 15, g = h >> 2;

    const float* P  = g_scores + (size_t)bh * TSEQ * TSEQ + (size_t)ti*128 * TSEQ;
    const float* Vt = g_vt + (size_t)(b*NGRP + g) * HD * TSEQ;

    extern __shared__ float sm[];
    const int tid = threadIdx.x, lane = tid & 31, wid = tid >> 5;
    const int wm = (wid >> 2) * 64, wn = (wid & 3) * 32;
    const int lr = lane >> 2, lc = lane & 3;
    const uint32_t smb = (uint32_t)__cvta_generic_to_shared(sm);

    const int r0 = tid >> 2,        cq0 = (tid & 3) * 4;
    const int r1 = (tid + 256) >> 2;
    const float* Asrc0 = P  + (size_t)r0 * TSEQ + cq0;
    const float* Asrc1 = P  + (size_t)r1 * TSEQ + cq0;
    const float* Bsrc0 = Vt + (size_t)r0 * TSEQ + cq0;
    const float* Bsrc1 = Vt + (size_t)r1 * TSEQ + cq0;
    const uint32_t Ad0 = smb + (uint32_t)(r0*16 + cq0) * 4;
    const uint32_t Ad1 = smb + (uint32_t)(r1*16 + cq0) * 4;
    const uint32_t Bd0 = smb + (uint32_t)(ASTN + r0*16 + cq0) * 4;
    const uint32_t Bd1 = smb + (uint32_t)(ASTN + r1*16 + cq0) * 4;

    const int nt = (ti + 1) * 8;
    auto issue = [&](int i) {
        uint32_t so = (uint32_t)(i & 3) * (STG * 4);
        int k0 = i << 4;
        cp16(Ad0 + so, Asrc0 + k0);
        cp16(Ad1 + so, Asrc1 + k0);
        cp16(Bd0 + so, Bsrc0 + k0);
        cp16(Bd1 + so, Bsrc1 + k0);
    };
    issue(0); cp_commit();
    issue(1); cp_commit();

    float acc[4][4][4];
    #pragma unroll
    for (int mt = 0; mt < 4; mt++)
        #pragma unroll
        for (int ntt = 0; ntt < 4; ntt++)
            #pragma unroll
            for (int i = 0; i < 4; i++) acc[mt][ntt][i] = 0.f;

    for (int i = 0; i < nt; i++) {
        if (i + 2 < nt) issue(i + 2);
        cp_commit();
        cp_wait2();
        __syncthreads();
        const float* As = sm + (size_t)(i & 3) * STG;
        stage_mma(As, As + ASTN, wm, wn, lr, lc, acc);
    }

    float* Y = g_y + (size_t)(b*TSEQ + ti*128) * CEMB + h*128;
    #pragma unroll
    for (int mt = 0; mt < 4; mt++) {
        int rr = wm + mt*16 + lr;
        #pragma unroll
        for (int ntt = 0; ntt < 4; ntt++) {
            int dd = wn + ntt*8 + lc*2;
            Y[(size_t)rr*CEMB + dd  ]     = to_tf32(acc[mt][ntt][0]);
            Y[(size_t)rr*CEMB + dd+1]     = to_tf32(acc[mt][ntt][1]);
            Y[(size_t)(rr+8)*CEMB + dd  ] = to_tf32(acc[mt][ntt][2]);
            Y[(size_t)(rr+8)*CEMB + dd+1] = to_tf32(acc[mt][ntt][3]);
        }
    }
}

// ---------------- launch ----------------------------------------------------
extern "C" void kernel_launch(void* const* d_in, const int* in_sizes, int n_in,
                              void* d_out, int out_size)
{
    (void)in_sizes; (void)n_in; (void)out_size;
    const float* x     = (const float*)d_in[0];
    const float* cosb  = (const float*)d_in[1];
    const float* sinb  = (const float*)d_in[2];
    const float* ln1w  = (const float*)d_in[3];
    const float* ln1b  = (const float*)d_in[4];
    const float* wqkv  = (const float*)d_in[5];
    const float* bqkv  = (const float*)d_in[6];
    const float* wproj = (const float*)d_in[7];
    const float* bproj = (const float*)d_in[8];
    const float* ln2w  = (const float*)d_in[9];
    const float* ln2b  = (const float*)d_in[10];
    const float* wfc1  = (const float*)d_in[11];
    const float* bfc1  = (const float*)d_in[12];
    const float* wfc2  = (const float*)d_in[13];
    const float* bfc2  = (const float*)d_in[14];
    float* out = (float*)d_out;

    float *xn1, *xn2, *qkv, *yv, *act, *wc;
    cudaGetSymbolAddress((void**)&xn1, g_xn1);
    cudaGetSymbolAddress((void**)&xn2, g_xn2);
    cudaGetSymbolAddress((void**)&qkv, g_qkv);
    cudaGetSymbolAddress((void**)&yv,  g_y);
    cudaGetSymbolAddress((void**)&act, g_act);
    cudaGetSymbolAddress((void**)&wc,  g_wcvt);
    float* wqkv_t  = wc;                 // [3072][2048]
    float* wproj_t = wc + 6291456;       // [2048][2048]
    float* wfc1_t  = wc + 10485760;      // [8192][2048]
    float* wfc2_t  = wc + 27262976;      // [2048][8192]

    cudaFuncSetAttribute(mm_pipe<EPI_CVT>,    cudaFuncAttributeMaxDynamicSharedMemorySize, MM_SMEM);
    cudaFuncSetAttribute(mm_pipe<EPI_RESID>,  cudaFuncAttributeMaxDynamicSharedMemorySize, MM_SMEM);
    cudaFuncSetAttribute(mm_pipe<EPI_GELU>,   cudaFuncAttributeMaxDynamicSharedMemorySize, MM_SMEM);
    cudaFuncSetAttribute(mm_pipe<EPI_ADDOUT>, cudaFuncAttributeMaxDynamicSharedMemorySize, MM_SMEM);
    cudaFuncSetAttribute(attn_scores_mma,     cudaFuncAttributeMaxDynamicSharedMemorySize, MM_SMEM);
    cudaFuncSetAttribute(attn_av_mma,         cudaFuncAttributeMaxDynamicSharedMemorySize, MM_SMEM);

    // 0. tf32-round + transpose all weights
    wtrans_kernel<<<dim3(QKVN/32, CEMB/32), 256>>>(wqkv,  wqkv_t,  CEMB, QKVN);
    wtrans_kernel<<<dim3(CEMB/32, CEMB/32), 256>>>(wproj, wproj_t, CEMB, CEMB);
    wtrans_kernel<<<dim3(FFN/32,  CEMB/32), 256>>>(wfc1,  wfc1_t,  CEMB, FFN);
    wtrans_kernel<<<dim3(CEMB/32, FFN/32),  256>>>(wfc2,  wfc2_t,  FFN,  CEMB);

    // 1. LN1 + LN2 (shared statistics, tf32-rounded outputs)
    ln_kernel<<<MROWS, 256>>>(x, ln1w, ln1b, ln2w, ln2b);

    // 2. QKV GEMM (tf32-rounded output)
    mm_pipe<EPI_CVT><<<dim3(QKVN/128, MROWS/128), 256, MM_SMEM>>>(
        xn1, wqkv_t, qkv, QKVN, bqkv, nullptr, CEMB);

    // 3. RoPE in-place, then V transpose for AV operand-major layout
    rope_kernel<<<MROWS, 320>>>(cosb, sinb);
    vtrans_kernel<<<dim3(TSEQ/32, HD/32, BATCH*NGRP), 256>>>();

    // 4-6. causal scores, softmax, P·V
    attn_scores_mma<<<dim3(16, 16, BATCH*NHEAD), 256, MM_SMEM>>>();
    softmax_kernel<<<dim3(TSEQ, BATCH*NHEAD), 128>>>();
    attn_av_mma<<<dim3(16, BATCH*NHEAD), 256, MM_SMEM>>>();

    // 7. proj GEMM (+b_proj + x residual) -> d_out
    mm_pipe<EPI_RESID><<<dim3(CEMB/128, MROWS/128), 256, MM_SMEM>>>(
        yv, wproj_t, out, CEMB, bproj, x, CEMB);

    // 8. fc1 GEMM + exact GELU (tf32-rounded)
    mm_pipe<EPI_GELU><<<dim3(FFN/128, MROWS/128), 256, MM_SMEM>>>(
        xn2, wfc1_t, act, FFN, bfc1, nullptr, CEMB);

    // 9. fc2 GEMM adds into d_out
    mm_pipe<EPI_ADDOUT><<<dim3(CEMB/128, MROWS/128), 256, MM_SMEM>>>(
        act, wfc2_t, out, CEMB, bfc2, nullptr, FFN);
}